// round 16
// baseline (speedup 1.0000x reference)
#include <cuda_runtime.h>
#include <cuda_fp16.h>
#include <cstdint>

constexpr int B = 4, L = 4096, H = 16, D = 64, M = 256, E = 64;
constexpr int BH = 64;
constexpr int NCHUNK = 8;
constexpr float SCALE = 0.35355339059327378f;  // 64^-0.25
constexpr float KEPS = 1e-3f;
constexpr float ZEPS = 1e-6f;

// ---- global scratch ----
__device__ float g_KVpart[(size_t)NCHUNK * BH * M * E];
__device__ float g_Kspart[(size_t)NCHUNK * BH * M];
__device__ __align__(16) __half g_KVh[(size_t)BH * M * E];
__device__ float g_Ksum[(size_t)BH * M];

// ---- smem byte offsets (kernel A: M-split, 64-row tiles, reg-prefetch) ----
constexpr int A_P = 0, A_X = 16384, A_V = 24576, A_F = 32768;
constexpr int SMEM_A = 49152;
// ---- smem byte offsets (kernel B: 64-row tiles) ----
constexpr int B_P = 0, B_X = 32768, B_F = 40960, B_KV = 73728, B_KS = 106496,
              B_ZP = 107520, B_SZ = 108544;
constexpr int SMEM_B = 108800;

// ============================ low-level helpers ============================
__device__ __forceinline__ uint32_t smem_u32(const void* p) {
    uint32_t a;
    asm("{ .reg .u64 t; cvta.to.shared.u64 t, %1; cvt.u32.u64 %0, t; }" : "=r"(a) : "l"(p));
    return a;
}
__device__ __forceinline__ void ldsm_x4(uint32_t a, uint32_t r[4]) {
    asm volatile("ldmatrix.sync.aligned.m8n8.x4.shared.b16 {%0,%1,%2,%3}, [%4];"
                 : "=r"(r[0]), "=r"(r[1]), "=r"(r[2]), "=r"(r[3]) : "r"(a));
}
__device__ __forceinline__ void ldsm_x4t(uint32_t a, uint32_t r[4]) {
    asm volatile("ldmatrix.sync.aligned.m8n8.x4.trans.shared.b16 {%0,%1,%2,%3}, [%4];"
                 : "=r"(r[0]), "=r"(r[1]), "=r"(r[2]), "=r"(r[3]) : "r"(a));
}
__device__ __forceinline__ void mma16816(float c[4], const uint32_t a[4], const uint32_t b[2]) {
    asm volatile(
        "mma.sync.aligned.m16n8k16.row.col.f32.f16.f16.f32 "
        "{%0,%1,%2,%3}, {%4,%5,%6,%7}, {%8,%9}, {%0,%1,%2,%3};"
        : "+f"(c[0]), "+f"(c[1]), "+f"(c[2]), "+f"(c[3])
        : "r"(a[0]), "r"(a[1]), "r"(a[2]), "r"(a[3]), "r"(b[0]), "r"(b[1]));
}
__device__ __forceinline__ void cp_async16(uint32_t dst, const void* src) {
    asm volatile("cp.async.cg.shared.global [%0], [%1], 16;" ::"r"(dst), "l"(src));
}
#define CP_COMMIT() asm volatile("cp.async.commit_group;" ::: "memory")
#define CP_WAIT0() asm volatile("cp.async.wait_group 0;" ::: "memory")

__device__ __forceinline__ uint32_t packh2(float x, float y) {
    __half2 h = __floats2half2_rn(x, y);
    return *(uint32_t*)&h;
}
__device__ __forceinline__ void pack_store8(float4 a, float4 b, char* hp) {
    uint4 hv;
    hv.x = packh2(a.x, a.y);
    hv.y = packh2(a.z, a.w);
    hv.z = packh2(b.x, b.y);
    hv.w = packh2(b.z, b.w);
    *(uint4*)hp = hv;
}
__device__ __forceinline__ uint32_t adr128(uint32_t base, int row, int chunk) {
    return base + row * 128 + ((chunk ^ (row & 7)) << 4);
}
__device__ __forceinline__ uint32_t adr256(uint32_t base, int row, int chunk) {
    return base + row * 256 + ((chunk ^ (row & 7)) << 4);
}
__device__ __forceinline__ uint32_t adr512(uint32_t base, int row, int chunk) {
    return base + row * 512 + ((chunk ^ (row & 7)) << 4);
}

// ============================ Kernel A: KV + Ksum partials ============================
// grid (2, BH, NCHUNK): mhalf fastest -> paired CTAs read identical k/v (L2 dedupe)
__global__ __launch_bounds__(256, 2) void kv_kernel(const float* __restrict__ k,
                                                    const float* __restrict__ v,
                                                    const float* __restrict__ P) {
    extern __shared__ char smem[];
    const uint32_t sb = smem_u32(smem);
    const int tid = threadIdx.x, w = tid >> 5, lane = tid & 31;
    const int ln = lane & 7, g2 = lane >> 3;
    const int mhalf = blockIdx.x;
    const int bh = blockIdx.y, b = bh >> 4, hd = bh & 15;
    const int chunk = blockIdx.z;
    const int lg = w & 3, quad = w >> 2;  // phi: rows lg*16, m-block quad*64 (in half)
    const int mt = w & 3, eh = w >> 2;    // KV: m mt*32, e eh*32
    const size_t cta_base = ((size_t)(b * L + chunk * 512) * H + hd) * 64;

    // this thread's two (l,ch) slots within a 64-row tile
    const int l0s = tid >> 3, ch0 = tid & 7;          // u = tid
    const int l1s = (tid + 256) >> 3, ch1 = tid & 7;  // u = tid + 256
    const size_t off0 = (size_t)l0s * 1024 + ch0 * 8;
    const size_t off1 = (size_t)l1s * 1024 + ch1 * 8;

    // prologue: LDG tile 0 k/v into held registers
    float4 hk[2][2], hv[2][2];
    hk[0][0] = *(const float4*)(k + cta_base + off0);
    hk[0][1] = *(const float4*)(k + cta_base + off0 + 4);
    hv[0][0] = *(const float4*)(v + cta_base + off0);
    hv[0][1] = *(const float4*)(v + cta_base + off0 + 4);
    hk[1][0] = *(const float4*)(k + cta_base + off1);
    hk[1][1] = *(const float4*)(k + cta_base + off1 + 4);
    hv[1][0] = *(const float4*)(v + cta_base + off1);
    hv[1][1] = *(const float4*)(v + cta_base + off1 + 4);

    // load P half (scaled), fp16, [128 rows x 128B]
    for (int u = tid; u < 1024; u += 256) {
        int ml = u >> 3, ch = u & 7;
        int mg = mhalf * 128 + ml;
        float4 p0 = *(const float4*)(P + mg * 64 + ch * 8);
        float4 p1 = *(const float4*)(P + mg * 64 + ch * 8 + 4);
        p0.x *= SCALE; p0.y *= SCALE; p0.z *= SCALE; p0.w *= SCALE;
        p1.x *= SCALE; p1.y *= SCALE; p1.z *= SCALE; p1.w *= SCALE;
        pack_store8(p0, p1, smem + A_P + adr128(0, ml, ch));
    }

    float kvacc[2][4][4];
    float ksacc[2][4];
#pragma unroll
    for (int mf = 0; mf < 2; mf++) {
#pragma unroll
        for (int i = 0; i < 4; i++) ksacc[mf][i] = 0.f;
#pragma unroll
        for (int n = 0; n < 4; n++)
#pragma unroll
            for (int i = 0; i < 4; i++) kvacc[mf][n][i] = 0.f;
    }
    const uint32_t onesb[2] = {0x3C003C00u, 0x3C003C00u};

    for (int t = 0; t < 8; t++) {
        __syncthreads();  // prior tile's X/V/F fully consumed
        // convert held regs -> fp16 X/V in smem
        pack_store8(hk[0][0], hk[0][1], smem + A_X + adr128(0, l0s, ch0));
        pack_store8(hv[0][0], hv[0][1], smem + A_V + adr128(0, l0s, ch0));
        pack_store8(hk[1][0], hk[1][1], smem + A_X + adr128(0, l1s, ch1));
        pack_store8(hv[1][0], hv[1][1], smem + A_V + adr128(0, l1s, ch1));
        __syncthreads();  // X/V ready
        if (t + 1 < 8) {  // prefetch next tile into held regs (lands during phi+KV)
            const size_t gbase = cta_base + (size_t)(t + 1) * 64 * 1024;
            hk[0][0] = *(const float4*)(k + gbase + off0);
            hk[0][1] = *(const float4*)(k + gbase + off0 + 4);
            hv[0][0] = *(const float4*)(v + gbase + off0);
            hv[0][1] = *(const float4*)(v + gbase + off0 + 4);
            hk[1][0] = *(const float4*)(k + gbase + off1);
            hk[1][1] = *(const float4*)(k + gbase + off1 + 4);
            hv[1][0] = *(const float4*)(v + gbase + off1);
            hv[1][1] = *(const float4*)(v + gbase + off1 + 4);
        }
        // phi: warp = 16l x 64m, K=64
        {
            float acc[8][4];
#pragma unroll
            for (int j = 0; j < 8; j++)
#pragma unroll
                for (int i = 0; i < 4; i++) acc[j][i] = 0.f;
            const int rowA = lg * 16 + ln + (g2 & 1) * 8;
#pragma unroll
            for (int kk = 0; kk < 4; kk++) {
                uint32_t ah[4];
                int cA = (2 * kk + (g2 >> 1)) ^ ln;
                ldsm_x4(sb + A_X + rowA * 128 + (cA << 4), ah);
                int cB = (2 * kk + (g2 & 1)) ^ ln;
#pragma unroll
                for (int j2 = 0; j2 < 4; j2++) {
                    uint32_t b4[4];
                    int rowB = quad * 64 + j2 * 16 + (g2 >> 1) * 8 + ln;
                    ldsm_x4(sb + A_P + rowB * 128 + (cB << 4), b4);
                    mma16816(acc[2 * j2], ah, b4);
                    mma16816(acc[2 * j2 + 1], ah, b4 + 2);
                }
            }
            // relu+eps, pack to F [64 rows x 256B]
            const int r0 = lg * 16 + (lane >> 2);
#pragma unroll
            for (int j = 0; j < 8; j++) {
                int ml = quad * 64 + j * 8 + 2 * (lane & 3);
                float f0 = fmaxf(acc[j][0], 0.f) + KEPS;
                float f1 = fmaxf(acc[j][1], 0.f) + KEPS;
                float f2 = fmaxf(acc[j][2], 0.f) + KEPS;
                float f3 = fmaxf(acc[j][3], 0.f) + KEPS;
                *(uint32_t*)(smem + A_F + adr256(0, r0, ml >> 3) + (ml & 7) * 2) =
                    packh2(f0, f1);
                *(uint32_t*)(smem + A_F + adr256(0, r0 + 8, ml >> 3) + (ml & 7) * 2) =
                    packh2(f2, f3);
            }
        }
        __syncthreads();  // F visible
        // KV: kvacc += F^T @ V over 64 l-rows; ksacc += F^T @ ones
#pragma unroll
        for (int kk = 0; kk < 4; kk++) {
            uint32_t fh[2][4];
            int rowAt = kk * 16 + (g2 >> 1) * 8 + ln;
#pragma unroll
            for (int mf = 0; mf < 2; mf++) {
                int cAt = (2 * (2 * mt + mf) + (g2 & 1)) ^ ln;
                ldsm_x4t(sb + A_F + rowAt * 256 + (cAt << 4), fh[mf]);
            }
            int rowBt = kk * 16 + (g2 & 1) * 8 + ln;
            uint32_t bv[2][4];
#pragma unroll
            for (int n2 = 0; n2 < 2; n2++) {
                int cBt = (eh * 4 + n2 * 2 + (g2 >> 1)) ^ ln;
                ldsm_x4t(sb + A_V + rowBt * 128 + (cBt << 4), bv[n2]);
            }
#pragma unroll
            for (int mf = 0; mf < 2; mf++) {
                mma16816(kvacc[mf][0], fh[mf], bv[0]);
                mma16816(kvacc[mf][1], fh[mf], bv[0] + 2);
                mma16816(kvacc[mf][2], fh[mf], bv[1]);
                mma16816(kvacc[mf][3], fh[mf], bv[1] + 2);
                mma16816(ksacc[mf], fh[mf], onesb);
            }
        }
    }
    // epilogue: write this half's partials
    float* dst = g_KVpart + (size_t)(chunk * BH + bh) * M * E + mhalf * 128 * 64;
    const int r = lane >> 2, c2 = 2 * (lane & 3);
#pragma unroll
    for (int mf = 0; mf < 2; mf++)
#pragma unroll
        for (int n = 0; n < 4; n++) {
            int m0 = mt * 32 + mf * 16 + r;
            int e = eh * 32 + n * 8 + c2;
            *(float2*)(dst + m0 * 64 + e) = make_float2(kvacc[mf][n][0], kvacc[mf][n][1]);
            *(float2*)(dst + (m0 + 8) * 64 + e) = make_float2(kvacc[mf][n][2], kvacc[mf][n][3]);
        }
    if (eh == 0 && (lane & 3) == 0) {
        float* kd = g_Kspart + (size_t)(chunk * BH + bh) * M + mhalf * 128;
#pragma unroll
        for (int mf = 0; mf < 2; mf++) {
            kd[mt * 32 + mf * 16 + r] = ksacc[mf][0];
            kd[mt * 32 + mf * 16 + r + 8] = ksacc[mf][2];
        }
    }
}

// ============================ reduce: partials -> KVh fp16 + Ksum (float4) ============================
__global__ void reduce_kernel() {
    int idx4 = blockIdx.x * 256 + threadIdx.x;  // one float4 per thread
    if (idx4 < BH * M * E / 4) {
        float4 s = make_float4(0.f, 0.f, 0.f, 0.f);
#pragma unroll
        for (int c = 0; c < NCHUNK; c++) {
            float4 p = *((const float4*)g_KVpart + (size_t)c * (BH * M * E / 4) + idx4);
            s.x += p.x; s.y += p.y; s.z += p.z; s.w += p.w;
        }
        uint2 hv;
        hv.x = packh2(s.x, s.y);
        hv.y = packh2(s.z, s.w);
        *((uint2*)g_KVh + idx4) = hv;
    }
    if (idx4 < BH * M / 4) {
        float4 s = make_float4(ZEPS, ZEPS, ZEPS, ZEPS);
#pragma unroll
        for (int c = 0; c < NCHUNK; c++) {
            float4 p = *((const float4*)g_Kspart + (size_t)c * (BH * M / 4) + idx4);
            s.x += p.x; s.y += p.y; s.z += p.z; s.w += p.w;
        }
        *((float4*)g_Ksum + idx4) = s;
    }
}

// ============================ Kernel B: out = (Qf @ KV) * Z ============================
__global__ __launch_bounds__(256, 2) void out_kernel(const float* __restrict__ q,
                                                     const float* __restrict__ P,
                                                     float* __restrict__ out) {
    extern __shared__ char smem[];
    const uint32_t sb = smem_u32(smem);
    const int tid = threadIdx.x, w = tid >> 5, lane = tid & 31;
    const int ln = lane & 7, g2 = lane >> 3;
    const int bh = blockIdx.x, b = bh >> 4, hd = bh & 15;
    const int lg = w & 1, mb = w >> 1;  // phi: rows lg*32, m-block mb*64
    const int lt = w & 3, eh = w >> 2;  // out: rows lt*16, e eh*32
    const size_t cta_base = ((size_t)(b * L + blockIdx.y * 512) * H + hd) * 64;

    const int l0s = tid >> 3, ch0 = tid & 7;
    const int l1s = (tid + 256) >> 3;
    const size_t off0 = (size_t)l0s * 1024 + ch0 * 8;
    const size_t off1 = (size_t)l1s * 1024 + ch0 * 8;

    // prologue: KVh (256x64 fp16) via cp.async + LDG q tile 0 into held regs
#pragma unroll
    for (int i = 0; i < 8; i++) {
        int c = tid + i * 256;
        int m = c >> 3, ch = c & 7;
        cp_async16(sb + B_KV + adr128(0, m, ch), g_KVh + (size_t)bh * 16384 + c * 8);
    }
    CP_COMMIT();
    float4 hq[2][2];
    hq[0][0] = *(const float4*)(q + cta_base + off0);
    hq[0][1] = *(const float4*)(q + cta_base + off0 + 4);
    hq[1][0] = *(const float4*)(q + cta_base + off1);
    hq[1][1] = *(const float4*)(q + cta_base + off1 + 4);
    // P full (scaled) fp16 [256 rows x 128B]
    for (int u = tid; u < 2048; u += 256) {
        int m = u >> 3, ch = u & 7;
        float4 p0 = *(const float4*)(P + m * 64 + ch * 8);
        float4 p1 = *(const float4*)(P + m * 64 + ch * 8 + 4);
        p0.x *= SCALE; p0.y *= SCALE; p0.z *= SCALE; p0.w *= SCALE;
        p1.x *= SCALE; p1.y *= SCALE; p1.z *= SCALE; p1.w *= SCALE;
        pack_store8(p0, p1, smem + B_P + adr128(0, m, ch));
    }
    ((float*)(smem + B_KS))[tid] = g_Ksum[(size_t)bh * M + tid];
    const float* sKsm = (const float*)(smem + B_KS);
    CP_WAIT0();

    for (int t = 0; t < 8; t++) {
        const size_t tbase = cta_base + (size_t)t * 64 * 1024;
        // convert held q -> fp16 X
        pack_store8(hq[0][0], hq[0][1], smem + B_X + adr128(0, l0s, ch0));
        pack_store8(hq[1][0], hq[1][1], smem + B_X + adr128(0, l1s, ch0));
        __syncthreads();  // X visible (KV prologue also, on t=0)
        if (t + 1 < 8) {  // prefetch next q tile
            const size_t gbase = cta_base + (size_t)(t + 1) * 64 * 1024;
            hq[0][0] = *(const float4*)(q + gbase + off0);
            hq[0][1] = *(const float4*)(q + gbase + off0 + 4);
            hq[1][0] = *(const float4*)(q + gbase + off1);
            hq[1][1] = *(const float4*)(q + gbase + off1 + 4);
        }
        float zp[2][2] = {{0.f, 0.f}, {0.f, 0.f}};
        {
            float acc[16][4];
#pragma unroll
            for (int j = 0; j < 16; j++)
#pragma unroll
                for (int i = 0; i < 4; i++) acc[j][i] = 0.f;
            const int R0 = lg * 32, MB = mb * 64;
            const int rowA0 = R0 + ln + (g2 & 1) * 8;
#pragma unroll
            for (int kk = 0; kk < 4; kk++) {
                uint32_t a0[4], a1[4];
                int cA = (2 * kk + (g2 >> 1)) ^ ln;
                ldsm_x4(sb + B_X + rowA0 * 128 + (cA << 4), a0);
                ldsm_x4(sb + B_X + (rowA0 + 16) * 128 + (cA << 4), a1);
                int cB = (2 * kk + (g2 & 1)) ^ ln;
#pragma unroll
                for (int j2 = 0; j2 < 4; j2++) {
                    uint32_t b4[4];
                    int rowB = MB + j2 * 16 + (g2 >> 1) * 8 + ln;
                    ldsm_x4(sb + B_P + rowB * 128 + (cB << 4), b4);
                    mma16816(acc[2 * j2], a0, b4);
                    mma16816(acc[2 * j2 + 1], a0, b4 + 2);
                    mma16816(acc[8 + 2 * j2], a1, b4);
                    mma16816(acc[8 + 2 * j2 + 1], a1, b4 + 2);
                }
            }
#pragma unroll
            for (int lsub = 0; lsub < 2; lsub++) {
                int r0 = R0 + lsub * 16 + (lane >> 2);
#pragma unroll
                for (int j = 0; j < 8; j++) {
                    int ml = MB + j * 8 + 2 * (lane & 3);
                    const float* a = acc[lsub * 8 + j];
                    float f0 = fmaxf(a[0], 0.f) + KEPS;
                    float f1 = fmaxf(a[1], 0.f) + KEPS;
                    float f2 = fmaxf(a[2], 0.f) + KEPS;
                    float f3 = fmaxf(a[3], 0.f) + KEPS;
                    *(uint32_t*)(smem + B_F + adr512(0, r0, ml >> 3) + (ml & 7) * 2) =
                        packh2(f0, f1);
                    *(uint32_t*)(smem + B_F + adr512(0, r0 + 8, ml >> 3) + (ml & 7) * 2) =
                        packh2(f2, f3);
                    float ks0 = sKsm[ml], ks1 = sKsm[ml + 1];
                    zp[lsub][0] += f0 * ks0 + f1 * ks1;
                    zp[lsub][1] += f2 * ks0 + f3 * ks1;
                }
            }
        }
        float* sZp = (float*)(smem + B_ZP);
#pragma unroll
        for (int lsub = 0; lsub < 2; lsub++)
#pragma unroll
            for (int rh = 0; rh < 2; rh++) {
                float z = zp[lsub][rh];
                z += __shfl_xor_sync(0xffffffffu, z, 1);
                z += __shfl_xor_sync(0xffffffffu, z, 2);
                if ((lane & 3) == 0) {
                    int row = lg * 32 + lsub * 16 + rh * 8 + (lane >> 2);
                    sZp[mb * 64 + row] = z;
                }
            }
        __syncthreads();  // F + sZp visible
        float* sZ = (float*)(smem + B_SZ);
        if (tid < 64)
            sZ[tid] = 1.0f / (sZp[tid] + sZp[64 + tid] + sZp[128 + tid] + sZp[192 + tid]);
        float oacc[4][4];
#pragma unroll
        for (int n = 0; n < 4; n++)
#pragma unroll
            for (int i = 0; i < 4; i++) oacc[n][i] = 0.f;
        {
            const int rowA = lt * 16 + ln + (g2 & 1) * 8;
#pragma unroll
            for (int kk = 0; kk < 16; kk++) {
                uint32_t qh[4];
                int cA = (2 * kk + (g2 >> 1)) ^ ln;
                ldsm_x4(sb + B_F + rowA * 512 + (cA << 4), qh);
                int rowB = kk * 16 + (g2 & 1) * 8 + ln;
#pragma unroll
                for (int n2 = 0; n2 < 2; n2++) {
                    uint32_t bkv[4];
                    int cB = (eh * 4 + n2 * 2 + (g2 >> 1)) ^ ln;
                    ldsm_x4t(sb + B_KV + rowB * 128 + (cB << 4), bkv);
                    mma16816(oacc[n2 * 2], qh, bkv);
                    mma16816(oacc[n2 * 2 + 1], qh, bkv + 2);
                }
            }
        }
        __syncthreads();  // sZ visible, F/X consumed
        const int r = lane >> 2, c2 = 2 * (lane & 3);
        const int l0 = lt * 16 + r;
        float z0 = sZ[l0], z1 = sZ[l0 + 8];
        size_t ob = tbase + (size_t)l0 * 1024;
#pragma unroll
        for (int n = 0; n < 4; n++) {
            int e = eh * 32 + n * 8 + c2;
            *(float2*)(out + ob + e) = make_float2(oacc[n][0] * z0, oacc[n][1] * z0);
            *(float2*)(out + ob + 8 * 1024 + e) = make_float2(oacc[n][2] * z1, oacc[n][3] * z1);
        }
    }
}

extern "C" void kernel_launch(void* const* d_in, const int* in_sizes, int n_in,
                              void* d_out, int out_size) {
    const float* q = (const float*)d_in[0];
    const float* k = (const float*)d_in[1];
    const float* v = (const float*)d_in[2];
    const float* P = (const float*)d_in[3];
    float* out = (float*)d_out;

    cudaFuncSetAttribute(kv_kernel, cudaFuncAttributeMaxDynamicSharedMemorySize, SMEM_A);
    cudaFuncSetAttribute(out_kernel, cudaFuncAttributeMaxDynamicSharedMemorySize, SMEM_B);

    kv_kernel<<<dim3(2, BH, NCHUNK), 256, SMEM_A>>>(k, v, P);
    reduce_kernel<<<dim3(BH * M * E / 4 / 256), 256>>>();
    out_kernel<<<dim3(BH, NCHUNK), 256, SMEM_B>>>(q, P, out);
}